// round 2
// baseline (speedup 1.0000x reference)
#include <cuda_runtime.h>
#include <math.h>

// Problem constants
#define BATCH 4
#define S 96                    // input spatial size
#define DP 48                   // output spatial size per dim
#define L (DP*DP*DP)            // 110592 tokens per batch
#define NTOK (BATCH*L)          // 442368 tokens total
#define DIM 64
#define EMB 64
#define MRF 32                  // number of random features
#define NCH 108                 // reduction chunks per batch (L / 1024)

// ---------------- scratch (device globals; no runtime allocation) ----------------
__device__ float g_kp[(size_t)NTOK * MRF];        // kp transposed: [m][n]
__device__ float g_qp[(size_t)NTOK * MRF];        // qp transposed: [m][n]
__device__ float g_v [(size_t)NTOK * EMB];        // v  transposed: [e][n]
__device__ float g_part_kptv[BATCH * NCH * EMB * MRF];
__device__ float g_part_ksum[BATCH * NCH * MRF];
__device__ float g_kptv[BATCH * EMB * MRF];       // [b][e][m]
__device__ float g_ksum[BATCH * MRF];             // [b][m]

// ============================================================================
// Pass 1: unfold + LN1 + kqv + prm_exp(k), prm_exp(q); store kp, qp, v
// One token per thread. Weights staged in shared memory (uniform broadcast).
// ============================================================================
__global__ __launch_bounds__(128) void pass1_kernel(
    const float* __restrict__ x,
    const float* __restrict__ ln1g, const float* __restrict__ ln1b,
    const float* __restrict__ wkqv, const float* __restrict__ bkqv,
    const float* __restrict__ wrf)
{
    __shared__ float s_w[64 * 64];     // current 64-row chunk of w_kqv
    __shared__ float s_wrf[MRF * 64];  // (32, 64)
    __shared__ float s_g[64], s_b[64], s_bias[64];

    const int t = threadIdx.x;
    const int n = blockIdx.x * 128 + t;

    // one-time shared loads
    for (int i = t; i < MRF * 64; i += 128) s_wrf[i] = wrf[i];
    if (t < 64) { s_g[t] = ln1g[t]; s_b[t] = ln1b[t]; }
    // K chunk (rows 0..63 of w_kqv)
    for (int i = t; i < 4096; i += 128) s_w[i] = wkqv[i];
    if (t < 64) s_bias[t] = bkqv[t];

    // ---- gather 4x4x4 patch (with pad=1, stride=2) ----
    const int b  = n / L;
    const int l  = n % L;
    const int d  = l / (DP * DP);
    const int hh = (l / DP) % DP;
    const int w  = l % DP;
    const float* xb = x + (size_t)b * S * S * S;

    float h[64];
    #pragma unroll
    for (int kd = 0; kd < 4; kd++) {
        const int iz = 2 * d - 1 + kd;
        const bool zok = (unsigned)iz < (unsigned)S;
        #pragma unroll
        for (int kh = 0; kh < 4; kh++) {
            const int iy = 2 * hh - 1 + kh;
            const bool yok = (unsigned)iy < (unsigned)S;
            #pragma unroll
            for (int kw = 0; kw < 4; kw++) {
                const int ix = 2 * w - 1 + kw;
                const bool ok = zok && yok && ((unsigned)ix < (unsigned)S);
                h[kd * 16 + kh * 4 + kw] = ok ? xb[(iz * S + iy) * S + ix] : 0.0f;
            }
        }
    }

    // ---- LayerNorm 1 ----
    float mu = 0.0f;
    #pragma unroll
    for (int f = 0; f < 64; f++) mu += h[f];
    mu *= (1.0f / 64.0f);
    float var = 0.0f;
    #pragma unroll
    for (int f = 0; f < 64; f++) { float dd = h[f] - mu; var += dd * dd; }
    var *= (1.0f / 64.0f);
    const float rs = rsqrtf(var + 1e-5f);

    __syncthreads();   // s_g/s_b/s_w/s_wrf ready

    #pragma unroll
    for (int f = 0; f < 64; f++) h[f] = (h[f] - mu) * rs * s_g[f] + s_b[f];

    const float rfscale = 0.1767766952966369f;   // 1/sqrt(32)

    // ---- K phase -> kp ----
    {
        float wtx[MRF];
        #pragma unroll
        for (int m = 0; m < MRF; m++) wtx[m] = 0.0f;
        float xd = 0.0f;
        for (int j = 0; j < 64; j++) {
            float acc = s_bias[j];
            #pragma unroll
            for (int k = 0; k < 64; k++) acc += h[k] * s_w[j * 64 + k];
            xd += acc * acc;
            #pragma unroll
            for (int m = 0; m < MRF; m++) wtx[m] += s_wrf[m * 64 + j] * acc;
        }
        #pragma unroll
        for (int m = 0; m < MRF; m++)
            g_kp[(size_t)m * NTOK + n] = expf(wtx[m] - 0.5f * xd) * rfscale;
    }

    __syncthreads();
    for (int i = t; i < 4096; i += 128) s_w[i] = wkqv[4096 + i];   // Q chunk
    if (t < 64) s_bias[t] = bkqv[64 + t];
    __syncthreads();

    // ---- Q phase -> qp ----
    {
        float wtx[MRF];
        #pragma unroll
        for (int m = 0; m < MRF; m++) wtx[m] = 0.0f;
        float xd = 0.0f;
        for (int j = 0; j < 64; j++) {
            float acc = s_bias[j];
            #pragma unroll
            for (int k = 0; k < 64; k++) acc += h[k] * s_w[j * 64 + k];
            xd += acc * acc;
            #pragma unroll
            for (int m = 0; m < MRF; m++) wtx[m] += s_wrf[m * 64 + j] * acc;
        }
        #pragma unroll
        for (int m = 0; m < MRF; m++)
            g_qp[(size_t)m * NTOK + n] = expf(wtx[m] - 0.5f * xd) * rfscale;
    }

    __syncthreads();
    for (int i = t; i < 4096; i += 128) s_w[i] = wkqv[8192 + i];   // V chunk
    if (t < 64) s_bias[t] = bkqv[128 + t];
    __syncthreads();

    // ---- V phase -> store v ----
    for (int j = 0; j < 64; j++) {
        float acc = s_bias[j];
        #pragma unroll
        for (int k = 0; k < 64; k++) acc += h[k] * s_w[j * 64 + k];
        g_v[(size_t)j * NTOK + n] = acc;
    }
}

// ============================================================================
// Reduce 1: per-chunk partial kptv[e][m] = sum_t v[t][e]*kp[t][m], kp_sum[m]
// grid (NCH, BATCH), 256 threads. Deterministic (no atomics).
// ============================================================================
__global__ __launch_bounds__(256) void reduce1_kernel()
{
    __shared__ float sv[64 * 65];
    __shared__ float sk[MRF * 65];

    const int b = blockIdx.y;
    const int c = blockIdx.x;
    const int t = threadIdx.x;
    const int n0 = b * L + c * 1024;

    const int e  = t >> 2;          // 0..63
    const int mb = (t & 3) * 8;     // 0,8,16,24

    float acc[8];
    #pragma unroll
    for (int i = 0; i < 8; i++) acc[i] = 0.0f;
    float ksum = 0.0f;

    for (int tile = 0; tile < 16; tile++) {
        const int base = n0 + tile * 64;
        __syncthreads();
        for (int idx = t; idx < 64 * 64; idx += 256) {
            const int ee = idx >> 6, tt = idx & 63;
            sv[ee * 65 + tt] = g_v[(size_t)ee * NTOK + base + tt];
        }
        for (int idx = t; idx < MRF * 64; idx += 256) {
            const int mm = idx >> 6, tt = idx & 63;
            sk[mm * 65 + tt] = g_kp[(size_t)mm * NTOK + base + tt];
        }
        __syncthreads();

        for (int tt = 0; tt < 64; tt++) {
            const float ve = sv[e * 65 + tt];
            #pragma unroll
            for (int i = 0; i < 8; i++) acc[i] += ve * sk[(mb + i) * 65 + tt];
        }
        if (t < MRF) {
            for (int tt = 0; tt < 64; tt++) ksum += sk[t * 65 + tt];
        }
    }

    const int slot = b * NCH + c;
    #pragma unroll
    for (int i = 0; i < 8; i++)
        g_part_kptv[slot * (EMB * MRF) + e * MRF + mb + i] = acc[i];
    if (t < MRF) g_part_ksum[slot * MRF + t] = ksum;
}

// ============================================================================
// Reduce 2: sum partials -> g_kptv[b], g_ksum[b]. grid BATCH, 256 threads.
// ============================================================================
__global__ __launch_bounds__(256) void reduce2_kernel()
{
    const int b = blockIdx.x;
    const int t = threadIdx.x;

    float acc[8];
    #pragma unroll
    for (int i = 0; i < 8; i++) acc[i] = 0.0f;
    for (int c = 0; c < NCH; c++) {
        const float* p = &g_part_kptv[(b * NCH + c) * (EMB * MRF)];
        #pragma unroll
        for (int i = 0; i < 8; i++) acc[i] += p[t * 8 + i];
    }
    #pragma unroll
    for (int i = 0; i < 8; i++) g_kptv[b * (EMB * MRF) + t * 8 + i] = acc[i];

    if (t < MRF) {
        float s = 0.0f;
        for (int c = 0; c < NCH; c++) s += g_part_ksum[(b * NCH + c) * MRF + t];
        g_ksum[b * MRF + t] = s;
    }
}

// ============================================================================
// Pass 2: y = v + proj(qp@kptv^T / D); out = y + MLP(LN2(y))
// One token per thread; weights staged in a reused shared buffer.
// stage A layout: [0..4095]=w_proj, [4096..6143]=kptv, [6144..6175]=ksum,
//                 [6176..6239]=b_proj
// stage B layout: [0..4095]=w_fc1, [4096..8191]=w_fc2, [8192..8255]=b_fc1,
//                 [8256..8319]=b_fc2, [8320..8383]=ln2g, [8384..8447]=ln2b
// ============================================================================
__global__ __launch_bounds__(128) void pass2_kernel(
    const float* __restrict__ wproj, const float* __restrict__ bproj,
    const float* __restrict__ ln2g,  const float* __restrict__ ln2b,
    const float* __restrict__ wfc1,  const float* __restrict__ bfc1,
    const float* __restrict__ wfc2,  const float* __restrict__ bfc2,
    float* __restrict__ out)
{
    __shared__ float sm[8448];

    const int t = threadIdx.x;
    const int n = blockIdx.x * 128 + t;
    const int b = n / L;   // all threads of a block share b (128 | L)

    // stage A
    for (int i = t; i < 4096; i += 128) sm[i] = wproj[i];
    for (int i = t; i < 2048; i += 128) sm[4096 + i] = g_kptv[b * 2048 + i];
    if (t < MRF) sm[6144 + t] = g_ksum[b * MRF + t];
    if (t < 64)  sm[6176 + t] = bproj[t];
    __syncthreads();

    float qp[MRF];
    #pragma unroll
    for (int m = 0; m < MRF; m++) qp[m] = g_qp[(size_t)m * NTOK + n];

    float D = 0.0f;
    #pragma unroll
    for (int m = 0; m < MRF; m++) D += qp[m] * sm[6144 + m];
    const float invD = 1.0f / (D + 1e-8f);

    float y[64];
    #pragma unroll
    for (int i = 0; i < 64; i++) y[i] = g_v[(size_t)i * NTOK + n] + sm[6176 + i];

    for (int j = 0; j < 64; j++) {
        float s = 0.0f;
        #pragma unroll
        for (int m = 0; m < MRF; m++) s += qp[m] * sm[4096 + j * MRF + m];
        const float ya = s * invD;
        #pragma unroll
        for (int i = 0; i < 64; i++) y[i] += sm[i * 64 + j] * ya;
    }

    // LN2 stats
    float mu = 0.0f;
    #pragma unroll
    for (int i = 0; i < 64; i++) mu += y[i];
    mu *= (1.0f / 64.0f);
    float var = 0.0f;
    #pragma unroll
    for (int i = 0; i < 64; i++) { float dd = y[i] - mu; var += dd * dd; }
    var *= (1.0f / 64.0f);
    const float rs = rsqrtf(var + 1e-5f);

    __syncthreads();
    // stage B
    for (int i = t; i < 4096; i += 128) sm[i] = wfc1[i];
    for (int i = t; i < 4096; i += 128) sm[4096 + i] = wfc2[i];
    if (t < 64) {
        sm[8192 + t] = bfc1[t];
        sm[8256 + t] = bfc2[t];
        sm[8320 + t] = ln2g[t];
        sm[8384 + t] = ln2b[t];
    }
    __syncthreads();

    float zn[64], acc[64];
    #pragma unroll
    for (int k = 0; k < 64; k++) {
        zn[k]  = (y[k] - mu) * rs * sm[8320 + k] + sm[8384 + k];
        acc[k] = y[k] + sm[8256 + k];
    }

    for (int j = 0; j < 64; j++) {
        float s = sm[8192 + j];
        #pragma unroll
        for (int k = 0; k < 64; k++) s += zn[k] * sm[j * 64 + k];
        const float u = 0.5f * s * (1.0f + erff(s * 0.7071067811865476f));
        #pragma unroll
        for (int i = 0; i < 64; i++) acc[i] += sm[4096 + i * 64 + j] * u;
    }

    float* op = out + (size_t)n * 64;
    #pragma unroll
    for (int i = 0; i < 64; i += 4) {
        float4 v4 = make_float4(acc[i], acc[i + 1], acc[i + 2], acc[i + 3]);
        *reinterpret_cast<float4*>(op + i) = v4;
    }
}

// ============================================================================
extern "C" void kernel_launch(void* const* d_in, const int* in_sizes, int n_in,
                              void* d_out, int out_size)
{
    const float* x     = (const float*)d_in[0];
    const float* ln1g  = (const float*)d_in[1];
    const float* ln1b  = (const float*)d_in[2];
    const float* wkqv  = (const float*)d_in[3];
    const float* bkqv  = (const float*)d_in[4];
    const float* wproj = (const float*)d_in[5];
    const float* bproj = (const float*)d_in[6];
    const float* ln2g  = (const float*)d_in[7];
    const float* ln2b  = (const float*)d_in[8];
    const float* wfc1  = (const float*)d_in[9];
    const float* bfc1  = (const float*)d_in[10];
    const float* wfc2  = (const float*)d_in[11];
    const float* bfc2  = (const float*)d_in[12];
    const float* wrf   = (const float*)d_in[13];

    pass1_kernel<<<NTOK / 128, 128>>>(x, ln1g, ln1b, wkqv, bkqv, wrf);
    reduce1_kernel<<<dim3(NCH, BATCH), 256>>>();
    reduce2_kernel<<<BATCH, 256>>>();
    pass2_kernel<<<NTOK / 128, 128>>>(wproj, bproj, ln2g, ln2b,
                                      wfc1, bfc1, wfc2, bfc2, (float*)d_out);
}

// round 3
// speedup vs baseline: 1.5165x; 1.5165x over previous
#include <cuda_runtime.h>
#include <math.h>

#define BATCH 4
#define S 96
#define DP 48
#define L (DP*DP*DP)            // 110592
#define NTOK (BATCH*L)          // 442368
#define MRF 32
#define NCH 108
#define TILE 128
#define NBLK (NTOK/TILE)        // 3456

typedef unsigned long long u64;

// ---------------- scratch ----------------
__device__ float g_kp[(size_t)NTOK * MRF];
__device__ float g_qp[(size_t)NTOK * MRF];
__device__ float g_v [(size_t)NTOK * 64];
__device__ float g_part_kptv[BATCH * NCH * 64 * MRF];
__device__ float g_part_ksum[BATCH * NCH * MRF];
__device__ float g_kptv[BATCH * 64 * MRF];
__device__ float g_ksum[BATCH * MRF];

// ---------------- f32x2 helpers ----------------
__device__ __forceinline__ u64 dup2(float v) {
    u64 r; asm("mov.b64 %0, {%1, %1};" : "=l"(r) : "f"(v)); return r;
}
__device__ __forceinline__ void fma2(u64 &d, u64 a, u64 b) {
    asm("fma.rn.f32x2 %0, %1, %2, %0;" : "+l"(d) : "l"(a), "l"(b));
}
__device__ __forceinline__ u64 mul2(u64 a, u64 b) {
    u64 r; asm("mul.rn.f32x2 %0, %1, %2;" : "=l"(r) : "l"(a), "l"(b)); return r;
}
__device__ __forceinline__ float2 up2(u64 v) {
    float lo, hi; asm("mov.b64 {%0, %1}, %2;" : "=f"(lo), "=f"(hi) : "l"(v));
    return make_float2(lo, hi);
}

// GEMM microkernel: 8 outputs x 4 tokens per thread, outputs packed in f32x2 pairs.
// sW: [K][WS] transposed weights (out-dim contiguous). sX: [K][128] tokens.
template<int KK, int WS>
__device__ __forceinline__ void mm8(const float* __restrict__ sW,
                                    const float* __restrict__ sX,
                                    int og, int tg, u64 acc[4][4])
{
    const float* wp = sW + og * 8;
    const float* xp = sX + tg * 4;
    #pragma unroll 8
    for (int k = 0; k < KK; k++) {
        u64 w0 = *(const u64*)(wp + k * WS);
        u64 w1 = *(const u64*)(wp + k * WS + 2);
        u64 w2 = *(const u64*)(wp + k * WS + 4);
        u64 w3 = *(const u64*)(wp + k * WS + 6);
        float4 xv = *(const float4*)(xp + k * 128);
        u64 x0 = dup2(xv.x), x1 = dup2(xv.y), x2 = dup2(xv.z), x3 = dup2(xv.w);
        fma2(acc[0][0], w0, x0); fma2(acc[0][1], w0, x1); fma2(acc[0][2], w0, x2); fma2(acc[0][3], w0, x3);
        fma2(acc[1][0], w1, x0); fma2(acc[1][1], w1, x1); fma2(acc[1][2], w1, x2); fma2(acc[1][3], w1, x3);
        fma2(acc[2][0], w2, x0); fma2(acc[2][1], w2, x1); fma2(acc[2][2], w2, x2); fma2(acc[2][3], w2, x3);
        fma2(acc[3][0], w3, x0); fma2(acc[3][1], w3, x1); fma2(acc[3][2], w3, x2); fma2(acc[3][3], w3, x3);
    }
}

// 4 outputs x 4 tokens per thread (for the 32-row random-feature GEMM).
template<int KK, int WS>
__device__ __forceinline__ void mm4(const float* __restrict__ sW,
                                    const float* __restrict__ sX,
                                    int mg, int tg, u64 acc[2][4])
{
    const float* wp = sW + mg * 4;
    const float* xp = sX + tg * 4;
    #pragma unroll 8
    for (int k = 0; k < KK; k++) {
        u64 w0 = *(const u64*)(wp + k * WS);
        u64 w1 = *(const u64*)(wp + k * WS + 2);
        float4 xv = *(const float4*)(xp + k * 128);
        u64 x0 = dup2(xv.x), x1 = dup2(xv.y), x2 = dup2(xv.z), x3 = dup2(xv.w);
        fma2(acc[0][0], w0, x0); fma2(acc[0][1], w0, x1); fma2(acc[0][2], w0, x2); fma2(acc[0][3], w0, x3);
        fma2(acc[1][0], w1, x0); fma2(acc[1][1], w1, x1); fma2(acc[1][2], w1, x2); fma2(acc[1][3], w1, x3);
    }
}

__device__ __forceinline__ void unpack44(const u64 acc[4][4], float res[8][4]) {
    #pragma unroll
    for (int p = 0; p < 4; p++)
        #pragma unroll
        for (int t = 0; t < 4; t++) {
            float2 f = up2(acc[p][t]);
            res[2 * p][t] = f.x; res[2 * p + 1][t] = f.y;
        }
}

// ============================================================================
// Pass 1: unfold + LN1 + kqv GEMMs + prm_exp; writes g_kp, g_qp, g_v
// ============================================================================
// smem layout (floats):
#define P1_SH   0        // [64][128]
#define P1_ST   8192     // [64][128]
#define P1_SW   16384    // [64][66]  transposed w chunk
#define P1_SWRF 20608    // [64][34]  transposed wrf
#define P1_SXD  22784    // [128]
#define P1_LNG  22912
#define P1_LNB  22976
#define P1_BIAS 23040
#define P1_SMEMF 23104
#define P1_SMEMB (P1_SMEMF*4)

__global__ __launch_bounds__(256, 2) void pass1_kernel(
    const float* __restrict__ x,
    const float* __restrict__ ln1g, const float* __restrict__ ln1b,
    const float* __restrict__ wkqv, const float* __restrict__ bkqv,
    const float* __restrict__ wrf)
{
    extern __shared__ float sm[];
    float* s_h    = sm + P1_SH;
    float* s_t    = sm + P1_ST;
    float* s_w    = sm + P1_SW;
    float* s_wrf  = sm + P1_SWRF;
    float* s_xd   = sm + P1_SXD;
    float* s_lng  = sm + P1_LNG;
    float* s_lnb  = sm + P1_LNB;
    float* s_bias = sm + P1_BIAS;

    const int tid = threadIdx.x;
    const int n0  = blockIdx.x * TILE;
    const int b   = n0 / L;
    const int l0  = n0 % L;

    // wrf transposed: s_wrf[j][m] = wrf[m][j] (coalesced global read)
    for (int i = tid; i < 2048; i += 256) {
        int m = i >> 6, j = i & 63;
        s_wrf[j * 34 + m] = wrf[i];
    }
    if (tid < 64) { s_lng[tid] = ln1g[tid]; s_lnb[tid] = ln1b[tid]; }

    // ---- gather + LN1 (2 threads per token) ----
    const int tok = tid >> 1, half = tid & 1;
    const int l  = l0 + tok;
    const int dz = l / (DP * DP), hy = (l / DP) % DP, wx = l % DP;
    const float* xb = x + (size_t)b * S * S * S;

    float hv[32];
    float sum = 0.0f, sq = 0.0f;
    #pragma unroll
    for (int kd2 = 0; kd2 < 2; kd2++) {
        const int iz = 2 * dz - 1 + half * 2 + kd2;
        const bool zok = (unsigned)iz < (unsigned)S;
        #pragma unroll
        for (int kh = 0; kh < 4; kh++) {
            const int iy = 2 * hy - 1 + kh;
            const bool yok = zok && ((unsigned)iy < (unsigned)S);
            #pragma unroll
            for (int kw = 0; kw < 4; kw++) {
                const int ix = 2 * wx - 1 + kw;
                const float v = (yok && (unsigned)ix < (unsigned)S)
                              ? xb[((size_t)iz * S + iy) * S + ix] : 0.0f;
                hv[kd2 * 16 + kh * 4 + kw] = v; sum += v; sq += v * v;
            }
        }
    }
    sum += __shfl_xor_sync(0xffffffffu, sum, 1);
    sq  += __shfl_xor_sync(0xffffffffu, sq, 1);
    const float mu  = sum * (1.0f / 64.0f);
    const float var = sq * (1.0f / 64.0f) - mu * mu;
    const float rs  = rsqrtf(var + 1e-5f);

    __syncthreads();   // s_lng/s_lnb (and s_wrf) ready
    #pragma unroll
    for (int i2 = 0; i2 < 32; i2++) {
        const int f = half * 32 + i2;
        s_h[f * 128 + tok] = (hv[i2] - mu) * rs * s_lng[f] + s_lnb[f];
    }

    const int og = tid >> 5, tg = tid & 31;
    const float rfscale = 0.1767766952966369f;   // 1/sqrt(32)

    for (int c = 0; c < 3; c++) {
        __syncthreads();
        // weight chunk transposed: s_w[k][o] = wkqv[c][o][k]
        for (int i = tid; i < 4096; i += 256) {
            int o = i >> 6, k = i & 63;
            s_w[k * 66 + o] = wkqv[c * 4096 + i];
        }
        if (tid < 64) s_bias[tid] = bkqv[c * 64 + tid];
        __syncthreads();

        u64 acc[4][4];
        #pragma unroll
        for (int p = 0; p < 4; p++) {
            u64 bv = *(const u64*)&s_bias[og * 8 + 2 * p];
            #pragma unroll
            for (int t4 = 0; t4 < 4; t4++) acc[p][t4] = bv;
        }
        mm8<64, 66>(s_w, s_h, og, tg, acc);

        if (c < 2) {
            float res[8][4];
            unpack44(acc, res);
            #pragma unroll
            for (int o = 0; o < 8; o++)
                *(float4*)&s_t[(og * 8 + o) * 128 + tg * 4] =
                    make_float4(res[o][0], res[o][1], res[o][2], res[o][3]);
            __syncthreads();
            if (tid < 128) {
                float s2 = 0.0f;
                #pragma unroll 8
                for (int j = 0; j < 64; j++) { float v = s_t[j * 128 + tid]; s2 += v * v; }
                s_xd[tid] = 0.5f * s2;
            }
            __syncthreads();

            u64 wa[2][4];
            #pragma unroll
            for (int p = 0; p < 2; p++)
                #pragma unroll
                for (int t4 = 0; t4 < 4; t4++) wa[p][t4] = 0ull;
            mm4<64, 34>(s_wrf, s_t, og, tg, wa);

            float wres[4][4];
            #pragma unroll
            for (int p = 0; p < 2; p++)
                #pragma unroll
                for (int t4 = 0; t4 < 4; t4++) {
                    float2 f = up2(wa[p][t4]);
                    wres[2 * p][t4] = f.x; wres[2 * p + 1][t4] = f.y;
                }
            const float4 xd4 = *(const float4*)&s_xd[tg * 4];
            float* dst = (c == 0) ? g_kp : g_qp;
            #pragma unroll
            for (int m2 = 0; m2 < 4; m2++) {
                float4 o4 = make_float4(
                    expf(wres[m2][0] - xd4.x) * rfscale,
                    expf(wres[m2][1] - xd4.y) * rfscale,
                    expf(wres[m2][2] - xd4.z) * rfscale,
                    expf(wres[m2][3] - xd4.w) * rfscale);
                *(float4*)&dst[(size_t)(og * 4 + m2) * NTOK + n0 + tg * 4] = o4;
            }
        } else {
            float res[8][4];
            unpack44(acc, res);
            #pragma unroll
            for (int o = 0; o < 8; o++)
                *(float4*)&g_v[(size_t)(og * 8 + o) * NTOK + n0 + tg * 4] =
                    make_float4(res[o][0], res[o][1], res[o][2], res[o][3]);
        }
    }
}

// ============================================================================
// Reduce 1 & 2: unchanged from R1 (deterministic two-stage kptv/ksum)
// ============================================================================
__global__ __launch_bounds__(256) void reduce1_kernel()
{
    __shared__ float sv[64 * 65];
    __shared__ float sk[MRF * 65];

    const int b = blockIdx.y;
    const int c = blockIdx.x;
    const int t = threadIdx.x;
    const int n0 = b * L + c * 1024;

    const int e  = t >> 2;
    const int mb = (t & 3) * 8;

    float acc[8];
    #pragma unroll
    for (int i = 0; i < 8; i++) acc[i] = 0.0f;
    float ksum = 0.0f;

    for (int tile = 0; tile < 16; tile++) {
        const int base = n0 + tile * 64;
        __syncthreads();
        for (int idx = t; idx < 64 * 64; idx += 256) {
            const int ee = idx >> 6, tt = idx & 63;
            sv[ee * 65 + tt] = g_v[(size_t)ee * NTOK + base + tt];
        }
        for (int idx = t; idx < MRF * 64; idx += 256) {
            const int mm = idx >> 6, tt = idx & 63;
            sk[mm * 65 + tt] = g_kp[(size_t)mm * NTOK + base + tt];
        }
        __syncthreads();

        for (int tt = 0; tt < 64; tt++) {
            const float ve = sv[e * 65 + tt];
            #pragma unroll
            for (int i = 0; i < 8; i++) acc[i] += ve * sk[(mb + i) * 65 + tt];
        }
        if (t < MRF) {
            for (int tt = 0; tt < 64; tt++) ksum += sk[t * 65 + tt];
        }
    }

    const int slot = b * NCH + c;
    #pragma unroll
    for (int i = 0; i < 8; i++)
        g_part_kptv[slot * (64 * MRF) + e * MRF + mb + i] = acc[i];
    if (t < MRF) g_part_ksum[slot * MRF + t] = ksum;
}

__global__ __launch_bounds__(256) void reduce2_kernel()
{
    const int b = blockIdx.x;
    const int t = threadIdx.x;

    float acc[8];
    #pragma unroll
    for (int i = 0; i < 8; i++) acc[i] = 0.0f;
    for (int c = 0; c < NCH; c++) {
        const float* p = &g_part_kptv[(b * NCH + c) * (64 * MRF)];
        #pragma unroll
        for (int i = 0; i < 8; i++) acc[i] += p[t * 8 + i];
    }
    #pragma unroll
    for (int i = 0; i < 8; i++) g_kptv[b * (64 * MRF) + t * 8 + i] = acc[i];

    if (t < MRF) {
        float s = 0.0f;
        for (int c = 0; c < NCH; c++) s += g_part_ksum[(b * NCH + c) * MRF + t];
        g_ksum[b * MRF + t] = s;
    }
}

// ============================================================================
// Pass 2: attn-apply + proj + skip + LN2 + MLP
// ============================================================================
#define P2_SY  0        // [64][128]
#define P2_SA  8192     // [64][128]
#define P2_SW  16384    // [64][66]
#define P2_SQP 20608    // [32][128]
#define P2_SKA 24704    // [32][66]
#define P2_SD  26816    // [128]
#define P2_SC  26944    // [352] consts
#define P2_SMEMF 27296
#define P2_SMEMB (P2_SMEMF*4)

__global__ __launch_bounds__(256, 2) void pass2_kernel(
    const float* __restrict__ wproj, const float* __restrict__ bproj,
    const float* __restrict__ ln2g,  const float* __restrict__ ln2b,
    const float* __restrict__ wfc1,  const float* __restrict__ bfc1,
    const float* __restrict__ wfc2,  const float* __restrict__ bfc2,
    float* __restrict__ out)
{
    extern __shared__ float sm[];
    float* s_y  = sm + P2_SY;
    float* s_a  = sm + P2_SA;
    float* s_w  = sm + P2_SW;
    float* s_qp = sm + P2_SQP;
    float* s_kA = sm + P2_SKA;
    float* s_d  = sm + P2_SD;
    float* s_c  = sm + P2_SC;

    const int tid = threadIdx.x;
    const int n0  = blockIdx.x * TILE;
    const int b   = n0 / L;

    // P0: stage qp tile, kptv^T, consts
    for (int i = tid; i < 1024; i += 256) {
        int m = i >> 5, t4 = i & 31;
        *(float4*)&s_qp[m * 128 + t4 * 4] =
            *(const float4*)&g_qp[(size_t)m * NTOK + n0 + t4 * 4];
    }
    for (int i = tid; i < 2048; i += 256) {
        int j = i >> 5, m = i & 31;
        s_kA[m * 66 + j] = g_kptv[b * 2048 + i];
    }
    if (tid < 64) {
        s_c[tid]       = bproj[tid];
        s_c[96 + tid]  = ln2g[tid];
        s_c[160 + tid] = ln2b[tid];
        s_c[224 + tid] = bfc1[tid];
        s_c[288 + tid] = bfc2[tid];
    }
    if (tid < 32) s_c[64 + tid] = g_ksum[b * 32 + tid];
    __syncthreads();

    if (tid < 128) {
        float D = 0.0f;
        #pragma unroll
        for (int m = 0; m < 32; m++) D += s_qp[m * 128 + tid] * s_c[64 + m];
        s_d[tid] = 1.0f / (D + 1e-8f);
    }
    __syncthreads();

    const int og = tid >> 5, tg = tid & 31;

    // P1: ya[j][t] = (kptv^T qp) * invD  -> s_a
    {
        u64 acc[4][4];
        #pragma unroll
        for (int p = 0; p < 4; p++)
            #pragma unroll
            for (int t4 = 0; t4 < 4; t4++) acc[p][t4] = 0ull;
        mm8<32, 66>(s_kA, s_qp, og, tg, acc);

        const float4 d4 = *(const float4*)&s_d[tg * 4];
        u64 dd[4] = { dup2(d4.x), dup2(d4.y), dup2(d4.z), dup2(d4.w) };
        #pragma unroll
        for (int p = 0; p < 4; p++)
            #pragma unroll
            for (int t4 = 0; t4 < 4; t4++) acc[p][t4] = mul2(acc[p][t4], dd[t4]);

        float res[8][4];
        unpack44(acc, res);
        #pragma unroll
        for (int o = 0; o < 8; o++)
            *(float4*)&s_a[(og * 8 + o) * 128 + tg * 4] =
                make_float4(res[o][0], res[o][1], res[o][2], res[o][3]);
    }
    __syncthreads();

    // P2: y = v + wproj @ ya + bproj -> s_y
    for (int i = tid; i < 4096; i += 256) {
        int o = i >> 6, k = i & 63;
        s_w[k * 66 + o] = wproj[i];
    }
    __syncthreads();
    {
        u64 acc[4][4];
        #pragma unroll
        for (int p = 0; p < 4; p++) {
            u64 bv = *(const u64*)&s_c[og * 8 + 2 * p];
            #pragma unroll
            for (int t4 = 0; t4 < 4; t4++) acc[p][t4] = bv;
        }
        mm8<64, 66>(s_w, s_a, og, tg, acc);

        float res[8][4];
        unpack44(acc, res);
        #pragma unroll
        for (int o = 0; o < 8; o++) {
            const int row = og * 8 + o;
            float4 vv = *(const float4*)&g_v[(size_t)row * NTOK + n0 + tg * 4];
            *(float4*)&s_y[row * 128 + tg * 4] = make_float4(
                res[o][0] + vv.x, res[o][1] + vv.y, res[o][2] + vv.z, res[o][3] + vv.w);
        }
    }
    __syncthreads();

    // P3: LN2 -> zn in s_a
    if (tid < 128) {
        float s1 = 0.0f, s2 = 0.0f;
        #pragma unroll 8
        for (int i = 0; i < 64; i++) { float v = s_y[i * 128 + tid]; s1 += v; s2 += v * v; }
        const float mu  = s1 * (1.0f / 64.0f);
        const float var = s2 * (1.0f / 64.0f) - mu * mu;
        const float rs  = rsqrtf(var + 1e-5f);
        #pragma unroll 8
        for (int k = 0; k < 64; k++)
            s_a[k * 128 + tid] = (s_y[k * 128 + tid] - mu) * rs * s_c[96 + k] + s_c[160 + k];
    }
    __syncthreads();

    // P4: u = gelu(wfc1 @ zn + bfc1) -> s_a (in place after sync)
    for (int i = tid; i < 4096; i += 256) {
        int o = i >> 6, k = i & 63;
        s_w[k * 66 + o] = wfc1[i];
    }
    __syncthreads();
    {
        u64 acc[4][4];
        #pragma unroll
        for (int p = 0; p < 4; p++) {
            u64 bv = *(const u64*)&s_c[224 + og * 8 + 2 * p];
            #pragma unroll
            for (int t4 = 0; t4 < 4; t4++) acc[p][t4] = bv;
        }
        mm8<64, 66>(s_w, s_a, og, tg, acc);
        __syncthreads();   // all reads of zn done before overwrite

        float res[8][4];
        unpack44(acc, res);
        #pragma unroll
        for (int o = 0; o < 8; o++) {
            float4 u4;
            float* up = &u4.x;
            #pragma unroll
            for (int t4 = 0; t4 < 4; t4++) {
                const float v = res[o][t4];
                up[t4] = 0.5f * v * (1.0f + erff(v * 0.7071067811865476f));
            }
            *(float4*)&s_a[(og * 8 + o) * 128 + tg * 4] = u4;
        }
    }
    __syncthreads();

    // P5: out = y + wfc2 @ u + bfc2
    for (int i = tid; i < 4096; i += 256) {
        int o = i >> 6, k = i & 63;
        s_w[k * 66 + o] = wfc2[i];
    }
    __syncthreads();
    {
        u64 acc[4][4];
        #pragma unroll
        for (int p = 0; p < 4; p++) {
            u64 bv = *(const u64*)&s_c[288 + og * 8 + 2 * p];
            #pragma unroll
            for (int t4 = 0; t4 < 4; t4++) acc[p][t4] = bv;
        }
        mm8<64, 66>(s_w, s_a, og, tg, acc);

        float res[8][4];
        unpack44(acc, res);
        #pragma unroll
        for (int o = 0; o < 8; o++) {
            const int row = og * 8 + o;
            float4 yy = *(const float4*)&s_y[row * 128 + tg * 4];
            res[o][0] += yy.x; res[o][1] += yy.y; res[o][2] += yy.z; res[o][3] += yy.w;
        }
        #pragma unroll
        for (int t4 = 0; t4 < 4; t4++) {
            const size_t n = (size_t)(n0 + tg * 4 + t4);
            *(float4*)&out[n * 64 + og * 8] =
                make_float4(res[0][t4], res[1][t4], res[2][t4], res[3][t4]);
            *(float4*)&out[n * 64 + og * 8 + 4] =
                make_float4(res[4][t4], res[5][t4], res[6][t4], res[7][t4]);
        }
    }
}

// ============================================================================
extern "C" void kernel_launch(void* const* d_in, const int* in_sizes, int n_in,
                              void* d_out, int out_size)
{
    const float* x     = (const float*)d_in[0];
    const float* ln1g  = (const float*)d_in[1];
    const float* ln1b  = (const float*)d_in[2];
    const float* wkqv  = (const float*)d_in[3];
    const float* bkqv  = (const float*)d_in[4];
    const float* wproj = (const float*)d_in[5];
    const float* bproj = (const float*)d_in[6];
    const float* ln2g  = (const float*)d_in[7];
    const float* ln2b  = (const float*)d_in[8];
    const float* wfc1  = (const float*)d_in[9];
    const float* bfc1  = (const float*)d_in[10];
    const float* wfc2  = (const float*)d_in[11];
    const float* bfc2  = (const float*)d_in[12];
    const float* wrf   = (const float*)d_in[13];

    cudaFuncSetAttribute(pass1_kernel, cudaFuncAttributeMaxDynamicSharedMemorySize, P1_SMEMB);
    cudaFuncSetAttribute(pass2_kernel, cudaFuncAttributeMaxDynamicSharedMemorySize, P2_SMEMB);

    pass1_kernel<<<NBLK, 256, P1_SMEMB>>>(x, ln1g, ln1b, wkqv, bkqv, wrf);
    reduce1_kernel<<<dim3(NCH, BATCH), 256>>>();
    reduce2_kernel<<<BATCH, 256>>>();
    pass2_kernel<<<NBLK, 256, P2_SMEMB>>>(wproj, bproj, ln2g, ln2b,
                                          wfc1, bfc1, wfc2, bfc2, (float*)d_out);
}